// round 3
// baseline (speedup 1.0000x reference)
#include <cuda_runtime.h>

// ---------------------------------------------------------------------------
// CustomFlashAttention — fp32 pipeline:
//   Q = X Wq^T ; K = X Wk^T ; V = X Wv^T          (gemm_tn)
//   O = softmax(Q K^T / sqrt(Hd)) V  per head      (fused flash attention)
//   out = O Wo^T                                   (gemm_tn)
// All hot loops use packed fma.rn.f32x2 (FFMA2): 2x fp32 throughput on sm_103a
// vs 3-register FFMA (rt 2 per SMSP either way, but FFMA2 does 2 FMA/lane).
// ---------------------------------------------------------------------------

#define SEQ     2048
#define DMODEL  2048
#define NHEADS  16
#define HDIM    128

// Scratch (device globals: no allocations allowed anywhere)
__device__ float g_Q[SEQ * DMODEL];
__device__ float g_K[SEQ * DMODEL];
__device__ float g_V[SEQ * DMODEL];
__device__ float g_O[SEQ * DMODEL];

typedef unsigned long long u64;

union F2U { u64 u; float2 f; };

__device__ __forceinline__ u64 dup2(float x) {
    u64 r;
    asm("mov.b64 %0, {%1, %1};" : "=l"(r) : "f"(x));
    return r;
}
__device__ __forceinline__ void ffma2(u64& d, u64 a, u64 b) {
    asm("fma.rn.f32x2 %0, %1, %2, %0;" : "+l"(d) : "l"(a), "l"(b));
}
__device__ __forceinline__ u64 fmul2(u64 a, u64 b) {
    u64 r;
    asm("mul.rn.f32x2 %0, %1, %2;" : "=l"(r) : "l"(a), "l"(b));
    return r;
}

// ---------------------------------------------------------------------------
// GEMM: C[M,N] = A[M,K] @ B[N,K]^T   (row-major, all dims multiples of tiles)
// 128x128 block tile, BK=16, 256 threads, 8x8 micro-tile (as 8 x 4 f32x2).
// ---------------------------------------------------------------------------
#define BM 128
#define BN 128
#define BK 16
#define GT 256

__global__ void __launch_bounds__(GT, 2) gemm_tn_kernel(
    const float* __restrict__ A, const float* __restrict__ B,
    float* __restrict__ C, int M, int N, int K)
{
    __shared__ float As[BK][BM];   // transposed: As[k][m]
    __shared__ float Bs[BK][BN];   // transposed: Bs[k][n]

    const int t  = threadIdx.x;
    const int tx = t & 15;         // N direction (8 cols = 4 pairs)
    const int ty = t >> 4;         // M direction (8 rows)
    const int m0 = blockIdx.y * BM;
    const int n0 = blockIdx.x * BN;

    u64 acc[8][4];
#pragma unroll
    for (int r = 0; r < 8; r++)
#pragma unroll
        for (int c = 0; c < 4; c++) acc[r][c] = 0ULL;

    const int nkt = K / BK;

    // prologue: stage 0 straight into SMEM
    {
#pragma unroll
        for (int i = 0; i < 2; i++) {
            int p = t + i * 256;           // 0..511 -> 512 float4 per matrix
            int row = p >> 2;              // 0..127
            int kq  = p & 3;               // which float4 along K
            float4 va = *(const float4*)(A + (m0 + row) * K + kq * 4);
            float4 vb = *(const float4*)(B + (n0 + row) * K + kq * 4);
            As[kq * 4 + 0][row] = va.x; As[kq * 4 + 1][row] = va.y;
            As[kq * 4 + 2][row] = va.z; As[kq * 4 + 3][row] = va.w;
            Bs[kq * 4 + 0][row] = vb.x; Bs[kq * 4 + 1][row] = vb.y;
            Bs[kq * 4 + 2][row] = vb.z; Bs[kq * 4 + 3][row] = vb.w;
        }
    }
    __syncthreads();

    float4 ra[2], rb[2];
    for (int kt = 1; kt <= nkt; kt++) {
        // prefetch next stage into registers
        if (kt < nkt) {
            int k0 = kt * BK;
#pragma unroll
            for (int i = 0; i < 2; i++) {
                int p = t + i * 256;
                int row = p >> 2, kq = p & 3;
                ra[i] = *(const float4*)(A + (m0 + row) * K + k0 + kq * 4);
                rb[i] = *(const float4*)(B + (n0 + row) * K + k0 + kq * 4);
            }
        }
        // compute current stage
#pragma unroll
        for (int kk = 0; kk < BK; kk++) {
            float4 a0 = *(const float4*)&As[kk][ty * 8];
            float4 a1 = *(const float4*)&As[kk][ty * 8 + 4];
            const u64* bp = (const u64*)&Bs[kk][tx * 8];
            u64 b0 = bp[0], b1 = bp[1], b2 = bp[2], b3 = bp[3];
            u64 ad[8];
            ad[0] = dup2(a0.x); ad[1] = dup2(a0.y);
            ad[2] = dup2(a0.z); ad[3] = dup2(a0.w);
            ad[4] = dup2(a1.x); ad[5] = dup2(a1.y);
            ad[6] = dup2(a1.z); ad[7] = dup2(a1.w);
#pragma unroll
            for (int r = 0; r < 8; r++) {
                ffma2(acc[r][0], ad[r], b0);
                ffma2(acc[r][1], ad[r], b1);
                ffma2(acc[r][2], ad[r], b2);
                ffma2(acc[r][3], ad[r], b3);
            }
        }
        __syncthreads();
        if (kt < nkt) {
#pragma unroll
            for (int i = 0; i < 2; i++) {
                int p = t + i * 256;
                int row = p >> 2, kq = p & 3;
                As[kq * 4 + 0][row] = ra[i].x; As[kq * 4 + 1][row] = ra[i].y;
                As[kq * 4 + 2][row] = ra[i].z; As[kq * 4 + 3][row] = ra[i].w;
                Bs[kq * 4 + 0][row] = rb[i].x; Bs[kq * 4 + 1][row] = rb[i].y;
                Bs[kq * 4 + 2][row] = rb[i].z; Bs[kq * 4 + 3][row] = rb[i].w;
            }
            __syncthreads();
        }
    }

    // epilogue: STG.64 per f32x2 pair
#pragma unroll
    for (int r = 0; r < 8; r++) {
        float* crow = C + (m0 + ty * 8 + r) * N + n0 + tx * 8;
#pragma unroll
        for (int c = 0; c < 4; c++) {
            *(u64*)(crow + c * 2) = acc[r][c];
        }
    }
}

// ---------------------------------------------------------------------------
// Fused flash attention, one block per (64-query tile, head).
// SMEM: Q^T[128][64], K^T[128][64], V[64][128], S[64][66] + row stats.
// Online softmax, O accumulator in registers (4 rows x 8 cols as f32x2).
// ---------------------------------------------------------------------------
#define BQ  64
#define BKT 64
#define AT  256
#define SS_LD 66   // padded row stride of the score tile

#define ATTN_SMEM_FLOATS (HDIM*BQ + HDIM*BKT + BKT*HDIM + BQ*SS_LD + 3*BQ)

__global__ void __launch_bounds__(AT) attn_kernel(
    const float* __restrict__ Q, const float* __restrict__ K,
    const float* __restrict__ V, float* __restrict__ O)
{
    extern __shared__ float sm[];
    float* Qst   = sm;                      // [HDIM][BQ]
    float* Kst   = Qst + HDIM * BQ;         // [HDIM][BKT]
    float* Vs    = Kst + HDIM * BKT;        // [BKT][HDIM]
    float* Ss    = Vs + BKT * HDIM;         // [BQ][SS_LD]
    float* row_m = Ss + BQ * SS_LD;
    float* row_l = row_m + BQ;
    float* row_f = row_l + BQ;

    const int t    = threadIdx.x;
    const int tx   = t & 15;
    const int ty   = t >> 4;
    const int q0   = blockIdx.x * BQ;
    const int hoff = blockIdx.y * HDIM;

    // load Q tile transposed: Qst[d][r]
#pragma unroll
    for (int i = 0; i < 8; i++) {
        int p = t + i * 256;               // 0..2047: 64 rows * 32 float4
        int row = p >> 5, c4 = p & 31;
        float4 v = *(const float4*)(Q + (q0 + row) * DMODEL + hoff + c4 * 4);
        Qst[(c4 * 4 + 0) * BQ + row] = v.x;
        Qst[(c4 * 4 + 1) * BQ + row] = v.y;
        Qst[(c4 * 4 + 2) * BQ + row] = v.z;
        Qst[(c4 * 4 + 3) * BQ + row] = v.w;
    }
    if (t < BQ) { row_m[t] = -1e30f; row_l[t] = 0.0f; }

    u64 o2[4][4];
#pragma unroll
    for (int i = 0; i < 4; i++)
#pragma unroll
        for (int c = 0; c < 4; c++) o2[i][c] = 0ULL;

    const float scale = 0.0883883476483184406f;  // 1/sqrt(128)

    for (int kt = 0; kt < SEQ / BKT; kt++) {
        const int kbase = kt * BKT;
        __syncthreads();   // previous phase-3 readers done with Kst/Vs

        // load K tile transposed + V tile natural
#pragma unroll
        for (int i = 0; i < 8; i++) {
            int p = t + i * 256;
            int row = p >> 5, c4 = p & 31;
            float4 kv = *(const float4*)(K + (kbase + row) * DMODEL + hoff + c4 * 4);
            Kst[(c4 * 4 + 0) * BKT + row] = kv.x;
            Kst[(c4 * 4 + 1) * BKT + row] = kv.y;
            Kst[(c4 * 4 + 2) * BKT + row] = kv.z;
            Kst[(c4 * 4 + 3) * BKT + row] = kv.w;
            float4 vv = *(const float4*)(V + (kbase + row) * DMODEL + hoff + c4 * 4);
            *(float4*)&Vs[row * HDIM + c4 * 4] = vv;
        }
        __syncthreads();

        // phase 2: S[64][64] = Q K^T * scale  (4 rows x 2 key-pairs / thread)
        {
            const int r0 = ty * 4, j0 = tx * 4;
            u64 s2[4][2];
#pragma unroll
            for (int i = 0; i < 4; i++) { s2[i][0] = 0ULL; s2[i][1] = 0ULL; }
#pragma unroll 4
            for (int d = 0; d < HDIM; d++) {
                float4 a = *(const float4*)&Qst[d * BQ + r0];
                const u64* kp = (const u64*)&Kst[d * BKT + j0];
                u64 b0 = kp[0], b1 = kp[1];
                u64 a0 = dup2(a.x), a1 = dup2(a.y), a2 = dup2(a.z), a3 = dup2(a.w);
                ffma2(s2[0][0], a0, b0); ffma2(s2[0][1], a0, b1);
                ffma2(s2[1][0], a1, b0); ffma2(s2[1][1], a1, b1);
                ffma2(s2[2][0], a2, b0); ffma2(s2[2][1], a2, b1);
                ffma2(s2[3][0], a3, b0); ffma2(s2[3][1], a3, b1);
            }
#pragma unroll
            for (int i = 0; i < 4; i++) {
                F2U u0, u1; u0.u = s2[i][0]; u1.u = s2[i][1];
                float* srow = &Ss[(r0 + i) * SS_LD + j0];
                srow[0] = u0.f.x * scale; srow[1] = u0.f.y * scale;
                srow[2] = u1.f.x * scale; srow[3] = u1.f.y * scale;
            }
        }
        __syncthreads();

        // softmax update: 4 threads per query row (16 scores each)
        {
            const int row = t >> 2;
            const int qd  = t & 3;
            float* srow = &Ss[row * SS_LD + qd * 16];
            float mloc = -1e30f;
#pragma unroll
            for (int j = 0; j < 16; j++) mloc = fmaxf(mloc, srow[j]);
            mloc = fmaxf(mloc, __shfl_xor_sync(0xffffffffu, mloc, 1));
            mloc = fmaxf(mloc, __shfl_xor_sync(0xffffffffu, mloc, 2));
            const float mold = row_m[row];
            const float mnew = fmaxf(mold, mloc);
            float lloc = 0.0f;
#pragma unroll
            for (int j = 0; j < 16; j++) {
                float p = __expf(srow[j] - mnew);
                srow[j] = p;
                lloc += p;
            }
            lloc += __shfl_xor_sync(0xffffffffu, lloc, 1);
            lloc += __shfl_xor_sync(0xffffffffu, lloc, 2);
            if (qd == 0) {
                float f = __expf(mold - mnew);
                row_f[row] = f;
                row_l[row] = row_l[row] * f + lloc;
                row_m[row] = mnew;
            }
        }
        __syncthreads();

        // phase 3: O = O*f + P V  (4 rows x 4 d-pairs / thread)
        {
            const int r0 = ty * 4, d0 = tx * 8;
#pragma unroll
            for (int i = 0; i < 4; i++) {
                u64 fd = dup2(row_f[r0 + i]);
                o2[i][0] = fmul2(o2[i][0], fd);
                o2[i][1] = fmul2(o2[i][1], fd);
                o2[i][2] = fmul2(o2[i][2], fd);
                o2[i][3] = fmul2(o2[i][3], fd);
            }
#pragma unroll 4
            for (int j = 0; j < BKT; j++) {
                const u64* vp = (const u64*)&Vs[j * HDIM + d0];
                u64 v0 = vp[0], v1 = vp[1], v2 = vp[2], v3 = vp[3];
#pragma unroll
                for (int i = 0; i < 4; i++) {
                    u64 pd = dup2(Ss[(r0 + i) * SS_LD + j]);
                    ffma2(o2[i][0], pd, v0);
                    ffma2(o2[i][1], pd, v1);
                    ffma2(o2[i][2], pd, v2);
                    ffma2(o2[i][3], pd, v3);
                }
            }
        }
    }

    // normalize and store
    {
        const int r0 = ty * 4, d0 = tx * 8;
#pragma unroll
        for (int i = 0; i < 4; i++) {
            u64 inv = dup2(1.0f / row_l[r0 + i]);
            float* orow = O + (q0 + r0 + i) * DMODEL + hoff + d0;
            *(u64*)(orow + 0) = fmul2(o2[i][0], inv);
            *(u64*)(orow + 2) = fmul2(o2[i][1], inv);
            *(u64*)(orow + 4) = fmul2(o2[i][2], inv);
            *(u64*)(orow + 6) = fmul2(o2[i][3], inv);
        }
    }
}

// ---------------------------------------------------------------------------
// Launch
// ---------------------------------------------------------------------------
extern "C" void kernel_launch(void* const* d_in, const int* in_sizes, int n_in,
                              void* d_out, int out_size)
{
    (void)in_sizes; (void)n_in; (void)out_size;

    const float* x  = (const float*)d_in[0];
    const float* wq = (const float*)d_in[1];
    const float* wk = (const float*)d_in[2];
    const float* wv = (const float*)d_in[3];
    const float* wo = (const float*)d_in[4];
    float* out = (float*)d_out;

    float *pQ, *pK, *pV, *pO;
    cudaGetSymbolAddress((void**)&pQ, g_Q);
    cudaGetSymbolAddress((void**)&pK, g_K);
    cudaGetSymbolAddress((void**)&pV, g_V);
    cudaGetSymbolAddress((void**)&pO, g_O);

    const int smem_attn = ATTN_SMEM_FLOATS * (int)sizeof(float);
    cudaFuncSetAttribute(attn_kernel,
                         cudaFuncAttributeMaxDynamicSharedMemorySize, smem_attn);

    dim3 gg(DMODEL / BN, SEQ / BM);
    gemm_tn_kernel<<<gg, GT>>>(x, wq, pQ, SEQ, DMODEL, DMODEL);
    gemm_tn_kernel<<<gg, GT>>>(x, wk, pK, SEQ, DMODEL, DMODEL);
    gemm_tn_kernel<<<gg, GT>>>(x, wv, pV, SEQ, DMODEL, DMODEL);

    attn_kernel<<<dim3(SEQ / BQ, NHEADS), AT, smem_attn>>>(pQ, pK, pV, pO);

    gemm_tn_kernel<<<gg, GT>>>(pO, wo, out, SEQ, DMODEL, DMODEL);
}